// round 9
// baseline (speedup 1.0000x reference)
#include <cuda_runtime.h>

#define NB     8
#define NATOM  512
#define NFEAT  42
#define NNEIGH 100
#define NPT    256
#define NH1    64
#define NH2    32

#define FT     384            // force kernel threads (divisible by 3!)
#define NPAIR  (NNEIGH*NFEAT) // 4200
#define NQ     (NPAIR*3/4)    // 3150 float4s per atom tile

// scratch for dE (input gradient), computed by ei_kernel, consumed by force_kernel
__device__ float g_dE[NB * NATOM * NFEAT];

// fast tanh: clamped exp-based, well within 1e-3 rel-err budget
__device__ __forceinline__ float fast_tanh(float x)
{
    x = fminf(15.0f, fmaxf(-15.0f, x));
    const float e = __expf(2.0f * x);
    return __fdividef(e - 1.0f, e + 1.0f);
}

// ---------------------------------------------------------------------------
// Kernel 1: per-atom MLP forward + backward, warp-per-atom.
// ---------------------------------------------------------------------------
__global__ __launch_bounds__(256) void ei_kernel(
    const float* __restrict__ image,
    const float* __restrict__ W0, const float* __restrict__ b0,
    const float* __restrict__ W1, const float* __restrict__ b1,
    const float* __restrict__ W2, const float* __restrict__ b2,
    float* __restrict__ out)
{
    __shared__ float sW0[NH1 * 43];
    __shared__ float sW1[NH2 * 65];
    __shared__ float sW2[NH2];
    __shared__ float sb0[NH1];
    __shared__ float sb1[NH2];
    __shared__ float sb2v;
    __shared__ float sx [8][NFEAT];
    __shared__ float sh1[8][NH1];
    __shared__ float sg2[8][NH2];
    __shared__ float sg1[8][NH1];

    const int tid = threadIdx.x;
    const int w   = tid >> 5;
    const int l   = tid & 31;

    const int base = blockIdx.x * 8;
    const int b    = base / NATOM;
    const int a0   = base % NATOM;
    const int t    = a0 / NPT;

    for (int i = tid; i < NH1 * NFEAT; i += 256) {
        int r = i / NFEAT, c = i - r * NFEAT;
        sW0[r * 43 + c] = W0[t * NH1 * NFEAT + i];
    }
    for (int i = tid; i < NH2 * NH1; i += 256) {
        int r = i >> 6, c = i & 63;
        sW1[r * 65 + c] = W1[t * NH2 * NH1 + i];
    }
    if (tid < NH2) sW2[tid] = W2[t * NH2 + tid];
    if (tid < NH1) sb0[tid] = b0[t * NH1 + tid];
    if (tid < NH2) sb1[tid] = b1[t * NH2 + tid];
    if (tid == 0)  sb2v = b2[t];
    __syncthreads();

    const int gidx = b * NATOM + (a0 + w);

    if (l < NFEAT)      sx[w][l]      = image[gidx * NFEAT + l];
    if (l < NFEAT - 32) sx[w][32 + l] = image[gidx * NFEAT + 32 + l];
    __syncwarp();

    float s1 = sb0[l], s2 = sb0[32 + l];
    #pragma unroll
    for (int f = 0; f < NFEAT; f++) {
        const float xv = sx[w][f];
        s1 += xv * sW0[l * 43 + f];
        s2 += xv * sW0[(32 + l) * 43 + f];
    }
    const float h1a = fast_tanh(s1), h1b = fast_tanh(s2);
    sh1[w][l] = h1a; sh1[w][32 + l] = h1b;
    __syncwarp();

    float s = sb1[l];
    #pragma unroll
    for (int i = 0; i < NH1; i++) s += sh1[w][i] * sW1[l * 65 + i];
    const float h2 = fast_tanh(s);
    const float w2v = sW2[l];
    sg2[w][l] = w2v * (1.0f - h2 * h2);

    float v = h2 * w2v;
    #pragma unroll
    for (int o = 16; o > 0; o >>= 1) v += __shfl_down_sync(0xffffffffu, v, o);
    if (l == 0) out[8 + gidx] = v + sb2v;
    __syncwarp();

    float t1 = 0.0f, t2 = 0.0f;
    #pragma unroll
    for (int j = 0; j < NH2; j++) {
        const float gv = sg2[w][j];
        t1 += gv * sW1[j * 65 + l];
        t2 += gv * sW1[j * 65 + 32 + l];
    }
    sg1[w][l]      = t1 * (1.0f - h1a * h1a);
    sg1[w][32 + l] = t2 * (1.0f - h1b * h1b);
    __syncwarp();

    const int c2 = (l < NFEAT - 32) ? (32 + l) : 0;
    float d1 = 0.0f, d2 = 0.0f;
    #pragma unroll
    for (int i = 0; i < NH1; i++) {
        const float gv = sg1[w][i];
        d1 += gv * sW0[i * 43 + l];
        d2 += gv * sW0[i * 43 + c2];
    }
    if (l < NFEAT)      g_dE[gidx * NFEAT + l]      = d1;
    if (l < NFEAT - 32) g_dE[gidx * NFEAT + 32 + l] = d2;
}

// ---------------------------------------------------------------------------
// Kernel 2: Force. 4096 blocks x 384 threads (384 % 3 == 0 is load-bearing).
// Compact 4200-float gathered tile (17KB smem -> high occupancy).
// Inner loop (specialized 3 ways on phase = tid%3): 1 LDG.128 + 2 LDS.32 +
// 4 FFMA. The 4 multiplier offsets only ever touch sg[m] and sg[m+1]; the
// slot pattern per phase is compile-time: (A,A,A,B) / (A,A,B,B) / (A,B,B,B).
// k(s) = (phase+s)%3 -> slot accumulators map to (x,y,z) once at the end.
// Blocks 0..7 also fold in the Etot reduction (deterministic order).
// ---------------------------------------------------------------------------

// One streaming pass with a compile-time slot->(A/B) pattern.
template<int O0, int O1, int O2, int O3>
__device__ __forceinline__ void stream_tile(
    const float4* __restrict__ df, const float* __restrict__ sg,
    int tid, int m0, float& a0, float& a1, float& a2, float& a3)
{
    #pragma unroll
    for (int it = 0; it < 8; it++) {            // q <= 383+2688 = 3071 < 3150
        const int q = tid + it * FT;
        const int m = m0 + it * 512;
        const float4 v = df[q];
        const float gA = sg[m];
        const float gB = sg[m + 1];
        a0 += (O0 ? gB : gA) * v.x;
        a1 += (O1 ? gB : gA) * v.y;
        a2 += (O2 ? gB : gA) * v.z;
        a3 += (O3 ? gB : gA) * v.w;
    }
    if (tid < NQ - 8 * FT) {                    // tail: 78 threads
        const int q = tid + 8 * FT;
        const int m = m0 + 8 * 512;
        const float4 v = df[q];
        const float gA = sg[m];
        const float gB = sg[m + 1];
        a0 += (O0 ? gB : gA) * v.x;
        a1 += (O1 ? gB : gA) * v.y;
        a2 += (O2 ? gB : gA) * v.z;
        a3 += (O3 ? gB : gA) * v.w;
    }
}

__global__ __launch_bounds__(FT) void force_kernel(
    const float* __restrict__ dfeat,
    const int* __restrict__ neighbor,
    float* __restrict__ out)
{
    __shared__ float sg[NPAIR];          // 4200 gathered dE values
    __shared__ int   sn[NNEIGH];
    __shared__ float red[FT / 32][3];
    __shared__ float sred[8];

    const int tid  = threadIdx.x;
    const int gidx = blockIdx.x;             // b*NATOM + a
    const int b    = gidx / NATOM;

    if (tid < NNEIGH)
        sn[tid] = neighbor[gidx * NNEIGH + tid];

    // fused Etot partial (blocks 0..7, first 256 threads): deterministic
    if (gidx < NB && tid < 256) {
        const float* Ei = out + 8 + gidx * NATOM;
        float v = Ei[tid] + Ei[tid + 256];
        #pragma unroll
        for (int o = 16; o > 0; o >>= 1) v += __shfl_down_sync(0xffffffffu, v, o);
        if ((tid & 31) == 0) sred[tid >> 5] = v;
    }
    __syncthreads();

    // Gather: one L2 load per (n,f) pair; index 0 -> zero pad row
    for (int p = tid; p < NPAIR; p += FT) {
        const int n = p / NFEAT;
        const int f = p - n * NFEAT;
        const int j = sn[n];
        sg[p] = j ? g_dE[(b * NATOM + (j - 1)) * NFEAT + f] : 0.0f;
    }
    __syncthreads();

    if (gidx < NB && tid == 0) {
        float s = 0.0f;
        #pragma unroll
        for (int ww = 0; ww < 8; ww++) s += sred[ww];
        out[gidx] = s;
    }

    const float4* __restrict__ df = (const float4*)(dfeat + (long)gidx * (NPAIR * 3));

    const int phase = tid % 3;               // == q mod 3 for all iterations
    const int m0    = (4 * tid) / 3;

    float a0 = 0.0f, a1 = 0.0f, a2 = 0.0f, a3 = 0.0f;

    // o_s = floor((phase + s)/3), s = 0..3
    if (phase == 0)      stream_tile<0,0,0,1>(df, sg, tid, m0, a0, a1, a2, a3);
    else if (phase == 1) stream_tile<0,0,1,1>(df, sg, tid, m0, a0, a1, a2, a3);
    else                 stream_tile<0,1,1,1>(df, sg, tid, m0, a0, a1, a2, a3);

    // map slot accumulators to (x,y,z):  k(s) = (phase + s) mod 3
    float ax, ay, az;
    if (phase == 0)      { ax = a0 + a3; ay = a1;      az = a2;      }
    else if (phase == 1) { ax = a2;      ay = a0 + a3; az = a1;      }
    else                 { ax = a1;      ay = a2;      az = a0 + a3; }

    #pragma unroll
    for (int o = 16; o > 0; o >>= 1) {
        ax += __shfl_down_sync(0xffffffffu, ax, o);
        ay += __shfl_down_sync(0xffffffffu, ay, o);
        az += __shfl_down_sync(0xffffffffu, az, o);
    }
    const int w = tid >> 5, l = tid & 31;
    if (l == 0) { red[w][0] = ax; red[w][1] = ay; red[w][2] = az; }
    __syncthreads();
    if (tid < 3) {
        float s = 0.0f;
        #pragma unroll
        for (int ww = 0; ww < FT / 32; ww++) s += red[ww][tid];
        out[8 + NB * NATOM + gidx * 3 + tid] = s;
    }
}

// ---------------------------------------------------------------------------
// Launch: out layout = [Etot(8) | Ei(4096) | Force(12288)] = 16392 f32
// ---------------------------------------------------------------------------
extern "C" void kernel_launch(void* const* d_in, const int* in_sizes, int n_in,
                              void* d_out, int out_size)
{
    const float* image    = (const float*)d_in[0];
    const float* dfeat    = (const float*)d_in[1];
    const int*   neighbor = (const int*)d_in[2];
    // d_in[3] = natoms_img (unused)
    const float* W0 = (const float*)d_in[4];
    const float* b0 = (const float*)d_in[5];
    const float* W1 = (const float*)d_in[6];
    const float* b1 = (const float*)d_in[7];
    const float* W2 = (const float*)d_in[8];
    const float* b2 = (const float*)d_in[9];
    float* out = (float*)d_out;

    ei_kernel<<<(NB * NATOM) / 8, 256>>>(image, W0, b0, W1, b1, W2, b2, out);
    force_kernel<<<NB * NATOM, FT>>>(dfeat, neighbor, out);
}

// round 10
// speedup vs baseline: 1.0869x; 1.0869x over previous
#include <cuda_runtime.h>

#define NB     8
#define NATOM  512
#define NFEAT  42
#define NNEIGH 100
#define NPT    256
#define NH1    64
#define NH2    32

#define FT     384            // force kernel threads (divisible by 3!)
#define NPAIR  (NNEIGH*NFEAT) // 4200
#define NQ     (NPAIR*3/4)    // 3150 float4s per atom tile

// scratch for dE (input gradient), computed by ei_kernel, consumed by force_kernel
__device__ float g_dE[NB * NATOM * NFEAT];

// fast tanh: clamped exp-based, well within 1e-3 rel-err budget
__device__ __forceinline__ float fast_tanh(float x)
{
    x = fminf(15.0f, fmaxf(-15.0f, x));
    const float e = __expf(2.0f * x);
    return __fdividef(e - 1.0f, e + 1.0f);
}

// ---------------------------------------------------------------------------
// Kernel 1: per-atom MLP forward + backward, warp-per-atom.
// ---------------------------------------------------------------------------
__global__ __launch_bounds__(256) void ei_kernel(
    const float* __restrict__ image,
    const float* __restrict__ W0, const float* __restrict__ b0,
    const float* __restrict__ W1, const float* __restrict__ b1,
    const float* __restrict__ W2, const float* __restrict__ b2,
    float* __restrict__ out)
{
    __shared__ float sW0[NH1 * 43];
    __shared__ float sW1[NH2 * 65];
    __shared__ float sW2[NH2];
    __shared__ float sb0[NH1];
    __shared__ float sb1[NH2];
    __shared__ float sb2v;
    __shared__ float sx [8][NFEAT];
    __shared__ float sh1[8][NH1];
    __shared__ float sg2[8][NH2];
    __shared__ float sg1[8][NH1];

    const int tid = threadIdx.x;
    const int w   = tid >> 5;
    const int l   = tid & 31;

    const int base = blockIdx.x * 8;
    const int b    = base / NATOM;
    const int a0   = base % NATOM;
    const int t    = a0 / NPT;

    for (int i = tid; i < NH1 * NFEAT; i += 256) {
        int r = i / NFEAT, c = i - r * NFEAT;
        sW0[r * 43 + c] = W0[t * NH1 * NFEAT + i];
    }
    for (int i = tid; i < NH2 * NH1; i += 256) {
        int r = i >> 6, c = i & 63;
        sW1[r * 65 + c] = W1[t * NH2 * NH1 + i];
    }
    if (tid < NH2) sW2[tid] = W2[t * NH2 + tid];
    if (tid < NH1) sb0[tid] = b0[t * NH1 + tid];
    if (tid < NH2) sb1[tid] = b1[t * NH2 + tid];
    if (tid == 0)  sb2v = b2[t];
    __syncthreads();

    const int gidx = b * NATOM + (a0 + w);

    if (l < NFEAT)      sx[w][l]      = image[gidx * NFEAT + l];
    if (l < NFEAT - 32) sx[w][32 + l] = image[gidx * NFEAT + 32 + l];
    __syncwarp();

    float s1 = sb0[l], s2 = sb0[32 + l];
    #pragma unroll
    for (int f = 0; f < NFEAT; f++) {
        const float xv = sx[w][f];
        s1 += xv * sW0[l * 43 + f];
        s2 += xv * sW0[(32 + l) * 43 + f];
    }
    const float h1a = fast_tanh(s1), h1b = fast_tanh(s2);
    sh1[w][l] = h1a; sh1[w][32 + l] = h1b;
    __syncwarp();

    float s = sb1[l];
    #pragma unroll
    for (int i = 0; i < NH1; i++) s += sh1[w][i] * sW1[l * 65 + i];
    const float h2 = fast_tanh(s);
    const float w2v = sW2[l];
    sg2[w][l] = w2v * (1.0f - h2 * h2);

    float v = h2 * w2v;
    #pragma unroll
    for (int o = 16; o > 0; o >>= 1) v += __shfl_down_sync(0xffffffffu, v, o);
    if (l == 0) out[8 + gidx] = v + sb2v;
    __syncwarp();

    float t1 = 0.0f, t2 = 0.0f;
    #pragma unroll
    for (int j = 0; j < NH2; j++) {
        const float gv = sg2[w][j];
        t1 += gv * sW1[j * 65 + l];
        t2 += gv * sW1[j * 65 + 32 + l];
    }
    sg1[w][l]      = t1 * (1.0f - h1a * h1a);
    sg1[w][32 + l] = t2 * (1.0f - h1b * h1b);
    __syncwarp();

    const int c2 = (l < NFEAT - 32) ? (32 + l) : 0;
    float d1 = 0.0f, d2 = 0.0f;
    #pragma unroll
    for (int i = 0; i < NH1; i++) {
        const float gv = sg1[w][i];
        d1 += gv * sW0[i * 43 + l];
        d2 += gv * sW0[i * 43 + c2];
    }
    if (l < NFEAT)      g_dE[gidx * NFEAT + l]      = d1;
    if (l < NFEAT - 32) g_dE[gidx * NFEAT + 32 + l] = d2;
}

// ---------------------------------------------------------------------------
// Kernel 2: Force. 4096 blocks x 384 threads (384 % 3 == 0 is load-bearing).
// R7 structure (uniform loop, NO per-lane branching) with two changes:
//  - entire dfeat stream (9 float4/thread) prefetched into registers BEFORE
//    the smem gather, overlapping DRAM latency with the L2 gather phase;
//  - multiplier fetch reduced to 2 LDS.32 (sg[m], sg[m+1]) + 2 data SELs:
//    o0 = 0 and o3 = 1 always; only slots 1,2 depend on phase = tid%3.
// k(s) = (phase+s)%3 -> slot accumulators map to (x,y,z) once at the end.
// Blocks 0..7 also fold in the Etot reduction (deterministic order).
// ---------------------------------------------------------------------------
__global__ __launch_bounds__(FT) void force_kernel(
    const float* __restrict__ dfeat,
    const int* __restrict__ neighbor,
    float* __restrict__ out)
{
    __shared__ float sg[NPAIR];          // 4200 gathered dE values
    __shared__ int   sn[NNEIGH];
    __shared__ float red[FT / 32][3];
    __shared__ float sred[8];

    const int tid  = threadIdx.x;
    const int gidx = blockIdx.x;             // b*NATOM + a
    const int b    = gidx / NATOM;

    if (tid < NNEIGH)
        sn[tid] = neighbor[gidx * NNEIGH + tid];

    // fused Etot partial (blocks 0..7, first 256 threads): deterministic
    if (gidx < NB && tid < 256) {
        const float* Ei = out + 8 + gidx * NATOM;
        float v = Ei[tid] + Ei[tid + 256];
        #pragma unroll
        for (int o = 16; o > 0; o >>= 1) v += __shfl_down_sync(0xffffffffu, v, o);
        if ((tid & 31) == 0) sred[tid >> 5] = v;
    }
    __syncthreads();

    // Prefetch the full dfeat stream into registers (independent of smem).
    const float4* __restrict__ df = (const float4*)(dfeat + (long)gidx * (NPAIR * 3));
    const bool tail_ok = tid < (NQ - 8 * FT);       // 78 tail threads
    float4 v[9];
    #pragma unroll
    for (int it = 0; it < 8; it++) v[it] = df[tid + it * FT];   // q <= 3071 < 3150
    v[8] = df[tail_ok ? (tid + 8 * FT) : tid];                  // clamped, in-bounds

    // Gather: one L2 load per (n,f) pair; index 0 -> zero pad row
    for (int p = tid; p < NPAIR; p += FT) {
        const int n = p / NFEAT;
        const int f = p - n * NFEAT;
        const int j = sn[n];
        sg[p] = j ? g_dE[(b * NATOM + (j - 1)) * NFEAT + f] : 0.0f;
    }
    __syncthreads();

    if (gidx < NB && tid == 0) {
        float s = 0.0f;
        #pragma unroll
        for (int ww = 0; ww < 8; ww++) s += sred[ww];
        out[gidx] = s;
    }

    const int  phase = tid % 3;              // == q mod 3 for all iterations
    const int  m0    = (4 * tid) / 3;
    const bool s1hi  = (phase == 2);         // slot1 uses gB iff phase==2
    const bool s2hi  = (phase >= 1);         // slot2 uses gB iff phase>=1

    float a0 = 0.0f, a1 = 0.0f, a2 = 0.0f, a3 = 0.0f;

    #pragma unroll
    for (int it = 0; it < 8; it++) {
        const int m = m0 + it * 512;
        const float gA = sg[m];
        const float gB = sg[m + 1];
        a0 += gA * v[it].x;
        a1 += (s1hi ? gB : gA) * v[it].y;
        a2 += (s2hi ? gB : gA) * v[it].z;
        a3 += gB * v[it].w;
    }
    if (tail_ok) {                           // m0 max 102 -> 4198+1 < 4200
        const int m = m0 + 8 * 512;
        const float gA = sg[m];
        const float gB = sg[m + 1];
        a0 += gA * v[8].x;
        a1 += (s1hi ? gB : gA) * v[8].y;
        a2 += (s2hi ? gB : gA) * v[8].z;
        a3 += gB * v[8].w;
    }

    // map slot accumulators to (x,y,z):  k(s) = (phase + s) mod 3
    float ax, ay, az;
    if (phase == 0)      { ax = a0 + a3; ay = a1;      az = a2;      }
    else if (phase == 1) { ax = a2;      ay = a0 + a3; az = a1;      }
    else                 { ax = a1;      ay = a2;      az = a0 + a3; }

    #pragma unroll
    for (int o = 16; o > 0; o >>= 1) {
        ax += __shfl_down_sync(0xffffffffu, ax, o);
        ay += __shfl_down_sync(0xffffffffu, ay, o);
        az += __shfl_down_sync(0xffffffffu, az, o);
    }
    const int w = tid >> 5, l = tid & 31;
    if (l == 0) { red[w][0] = ax; red[w][1] = ay; red[w][2] = az; }
    __syncthreads();
    if (tid < 3) {
        float s = 0.0f;
        #pragma unroll
        for (int ww = 0; ww < FT / 32; ww++) s += red[ww][tid];
        out[8 + NB * NATOM + gidx * 3 + tid] = s;
    }
}

// ---------------------------------------------------------------------------
// Launch: out layout = [Etot(8) | Ei(4096) | Force(12288)] = 16392 f32
// ---------------------------------------------------------------------------
extern "C" void kernel_launch(void* const* d_in, const int* in_sizes, int n_in,
                              void* d_out, int out_size)
{
    const float* image    = (const float*)d_in[0];
    const float* dfeat    = (const float*)d_in[1];
    const int*   neighbor = (const int*)d_in[2];
    // d_in[3] = natoms_img (unused)
    const float* W0 = (const float*)d_in[4];
    const float* b0 = (const float*)d_in[5];
    const float* W1 = (const float*)d_in[6];
    const float* b1 = (const float*)d_in[7];
    const float* W2 = (const float*)d_in[8];
    const float* b2 = (const float*)d_in[9];
    float* out = (float*)d_out;

    ei_kernel<<<(NB * NATOM) / 8, 256>>>(image, W0, b0, W1, b1, W2, b2, out);
    force_kernel<<<NB * NATOM, FT>>>(dfeat, neighbor, out);
}